// round 8
// baseline (speedup 1.0000x reference)
#include <cuda_runtime.h>
#include <cuda_fp16.h>
#include <mma.h>
#include <cstdint>

using namespace nvcuda;

#define BB 4
#define SS 2048
#define DD 512
#define HH 8
#define HD 64
#define LDH 72   // half leading dim
#define LDF 68   // float leading dim

// q = x @ Wq, pre-split into fp16 hi/lo pairs (packed half2 per uint32)
__device__ uint32_t g_qh[(size_t)BB * SS * DD / 2];
__device__ uint32_t g_ql[(size_t)BB * SS * DD / 2];

__device__ __forceinline__ float f16hi(float v) {
    return __half2float(__float2half_rn(v));
}
__device__ __forceinline__ uint32_t packh2(float a, float b) {
    __half2 h = __floats2half2_rn(a, b);
    return *(uint32_t*)&h;
}

// ---------------------------------------------------------------------------
// Kernel 1: q = x @ Wq  via fp16 wmma, 3-term split (hi,lo).  (unchanged)
// ---------------------------------------------------------------------------
__global__ __launch_bounds__(256) void qproj_kernel(const float* __restrict__ x,
                                                    const float* __restrict__ w) {
    __shared__ __align__(16) __half Ah[64 * LDH];
    __shared__ __align__(16) __half Al[64 * LDH];
    __shared__ __align__(16) __half Bh[64 * LDH];
    __shared__ __align__(16) __half Bl[64 * LDH];

    const int tid  = threadIdx.x;
    const int warp = tid >> 5;
    const int tr   = warp >> 1;
    const int tcb  = (warp & 1) * 2;
    const int bm   = blockIdx.x;
    const int bn   = blockIdx.y;

    wmma::fragment<wmma::accumulator, 16, 16, 16, float> c[2];
    wmma::fill_fragment(c[0], 0.f);
    wmma::fill_fragment(c[1], 0.f);

    const float* xbase = x + (size_t)bm * 64 * DD;

    for (int k0 = 0; k0 < DD; k0 += 64) {
#pragma unroll
        for (int i = tid; i < 1024; i += 256) {
            int rr = i >> 4, c4 = (i & 15) << 2;
            float4 a = *(const float4*)(xbase + (size_t)rr * DD + k0 + c4);
            float4 b = *(const float4*)(w + (size_t)(k0 + rr) * DD + bn * 64 + c4);
            uint32_t* Ahp = (uint32_t*)(Ah + rr * LDH + c4);
            uint32_t* Alp = (uint32_t*)(Al + rr * LDH + c4);
            uint32_t* Bhp = (uint32_t*)(Bh + rr * LDH + c4);
            uint32_t* Blp = (uint32_t*)(Bl + rr * LDH + c4);
            Ahp[0] = packh2(a.x, a.y);
            Ahp[1] = packh2(a.z, a.w);
            Alp[0] = packh2(a.x - f16hi(a.x), a.y - f16hi(a.y));
            Alp[1] = packh2(a.z - f16hi(a.z), a.w - f16hi(a.w));
            Bhp[0] = packh2(b.x, b.y);
            Bhp[1] = packh2(b.z, b.w);
            Blp[0] = packh2(b.x - f16hi(b.x), b.y - f16hi(b.y));
            Blp[1] = packh2(b.z - f16hi(b.z), b.w - f16hi(b.w));
        }
        __syncthreads();

#pragma unroll
        for (int kk = 0; kk < 64; kk += 16) {
            wmma::fragment<wmma::matrix_a, 16, 16, 16, __half, wmma::row_major> a_h, a_l;
            wmma::load_matrix_sync(a_h, Ah + tr * 16 * LDH + kk, LDH);
            wmma::load_matrix_sync(a_l, Al + tr * 16 * LDH + kk, LDH);
#pragma unroll
            for (int t = 0; t < 2; t++) {
                wmma::fragment<wmma::matrix_b, 16, 16, 16, __half, wmma::row_major> b_h, b_l;
                wmma::load_matrix_sync(b_h, Bh + kk * LDH + (tcb + t) * 16, LDH);
                wmma::load_matrix_sync(b_l, Bl + kk * LDH + (tcb + t) * 16, LDH);
                wmma::mma_sync(c[t], a_h, b_h, c[t]);
                wmma::mma_sync(c[t], a_l, b_h, c[t]);
                wmma::mma_sync(c[t], a_h, b_l, c[t]);
            }
        }
        __syncthreads();
    }

    float* Cs = (float*)Ah;
#pragma unroll
    for (int t = 0; t < 2; t++)
        wmma::store_matrix_sync(Cs + tr * 16 * LDF + (tcb + t) * 16, c[t], LDF, wmma::mem_row_major);
    __syncthreads();

#pragma unroll
    for (int i = tid; i < 2048; i += 256) {
        int rr = i >> 5, wv = i & 31;
        float c0 = Cs[rr * LDF + 2 * wv];
        float c1 = Cs[rr * LDF + 2 * wv + 1];
        size_t word = (size_t)(bm * 64 + rr) * (DD / 2) + bn * 32 + wv;
        g_qh[word] = packh2(c0, c1);
        g_ql[word] = packh2(c0 - f16hi(c0), c1 - f16hi(c1));
    }
}

// ---------------------------------------------------------------------------
// Kernel 2: flash attention. 128 threads, 4 warps; each warp owns a full
// 32(q) x 64(k) strip -> softmax & P entirely warp-local (no mid-iter sync).
// K tile double-buffered with register prefetch; ONE __syncthreads per tile.
// Static per-row shift m_i = 0.125*|q_i|^2.
// ---------------------------------------------------------------------------
#define OQH   0u
#define OQL   18432u
#define OKH0  36864u
#define OKL0  46080u
#define OKH1  55296u
#define OKL1  64512u
#define OPH   73728u     // also fp32 epilogue buffer (34816 <= 36864)
#define OPL   92160u
#define OIDX  110592u    // 16x16 fp32 index matrix
#define OMR   111616u    // mrow: 128 f32
#define OLR   112128u    // lrow: 128 f32
#define ATTN_SMEM_BYTES 112640

__global__ __launch_bounds__(128) void attn_kernel(float* __restrict__ out) {
    extern __shared__ __align__(16) char dsm[];
    __half* Qh = (__half*)(dsm + OQH);
    __half* Ql = (__half*)(dsm + OQL);
    __half* KhB[2] = { (__half*)(dsm + OKH0), (__half*)(dsm + OKH1) };
    __half* KlB[2] = { (__half*)(dsm + OKL0), (__half*)(dsm + OKL1) };
    __half* Ph = (__half*)(dsm + OPH);
    __half* Pl = (__half*)(dsm + OPL);
    float*  Idx  = (float*)(dsm + OIDX);
    float*  mrow = (float*)(dsm + OMR);
    float*  lrow = (float*)(dsm + OLR);

    const int tid  = threadIdx.x;
    const int warp = tid >> 5;            // 0..3 : owns q rows [warp*32, +32)
    const int qblk = blockIdx.x;          // 0..15
    const int bh   = blockIdx.y;          // 0..31
    const int b = bh >> 3, h = bh & 7;

    const uint4* gqh = (const uint4*)g_qh;
    const uint4* gql = (const uint4*)g_ql;

    // ---- load Q tile (128 x 64), index matrix, init lrow ----
#pragma unroll
    for (int i = tid; i < 1024; i += 128) {
        int r = i >> 3, c = i & 7;
        size_t idx = (size_t)(b * SS + qblk * 128 + r) * 64 + h * 8 + c;
        *(uint4*)(Qh + r * LDH + c * 8) = gqh[idx];
        *(uint4*)(Ql + r * LDH + c * 8) = gql[idx];
    }
    Idx[tid] = (float)tid;
    Idx[tid + 128] = (float)(tid + 128);
    lrow[tid] = 0.f;
    __syncthreads();

    // per-row static shift m_i = 0.125 * |q_i|^2 (one row per thread)
    {
        float n2 = 0.f;
#pragma unroll
        for (int c = 0; c < 64; c++) {
            float v = __half2float(Qh[tid * LDH + c]) + __half2float(Ql[tid * LDH + c]);
            n2 = fmaf(v, v, n2);
        }
        mrow[tid] = 0.125f * n2;
    }
    __syncthreads();

    // ---- runtime fragment layout discovery ----
    wmma::fragment<wmma::accumulator, 16, 16, 16, float> idxf;
    wmma::load_matrix_sync(idxf, Idx, 16, wmma::mem_row_major);
    int er[8], ec[8];
#pragma unroll
    for (int i = 0; i < 8; i++) {
        int e = (int)idxf.x[i];
        er[i] = e >> 4;
        ec[i] = e & 15;
    }
    bool paired = true;
#pragma unroll
    for (int i = 0; i < 8; i += 2)
        paired = paired && (er[i + 1] == er[i]) && (ec[i + 1] == ec[i] + 1) && ((ec[i] & 1) == 0);
    paired = __all_sync(0xFFFFFFFFu, paired);

    float mreg[2][8];
#pragma unroll
    for (int fr = 0; fr < 2; fr++)
#pragma unroll
        for (int i = 0; i < 8; i++)
            mreg[fr][i] = mrow[warp * 32 + fr * 16 + er[i]];

    float lacc[2][8];
#pragma unroll
    for (int fr = 0; fr < 2; fr++)
#pragma unroll
        for (int i = 0; i < 8; i++) lacc[fr][i] = 0.f;

    wmma::fragment<wmma::accumulator, 16, 16, 16, float> o[2][4];
#pragma unroll
    for (int fr = 0; fr < 2; fr++)
#pragma unroll
        for (int fc = 0; fc < 4; fc++) wmma::fill_fragment(o[fr][fc], 0.f);

    // ---- K prefetch lambda-equivalents (thread covers half a K row) ----
    const int kr = tid >> 1;          // K-tile row 0..63
    const int kc = tid & 1;           // which half (4 uint4)
    uint4 pf_h[4], pf_l[4];

    // prologue: fetch + store K tile 0 into buf 0
    {
        size_t gb = (size_t)(b * SS + kr) * 64 + h * 8 + kc * 4;
#pragma unroll
        for (int c = 0; c < 4; c++) { pf_h[c] = gqh[gb + c]; pf_l[c] = gql[gb + c]; }
#pragma unroll
        for (int c = 0; c < 4; c++) {
            *(uint4*)(KhB[0] + kr * LDH + kc * 32 + c * 8) = pf_h[c];
            *(uint4*)(KlB[0] + kr * LDH + kc * 32 + c * 8) = pf_l[c];
        }
    }

    const int NT = SS / 64;
    for (int j = 0; j < NT; j++) {
        const int cb = j & 1;
        __syncthreads();   // K buf cb writes visible; prev reads of buf 1-cb done

        // prefetch next K tile into registers (latency hidden under S-MMA)
        if (j + 1 < NT) {
            size_t gb = (size_t)(b * SS + (j + 1) * 64 + kr) * 64 + h * 8 + kc * 4;
#pragma unroll
            for (int c = 0; c < 4; c++) { pf_h[c] = gqh[gb + c]; pf_l[c] = gql[gb + c]; }
        }

        const __half* Kh = KhB[cb];
        const __half* Kl = KlB[cb];

        // ---- S = Q K^T (3-term fp16), warp strip 32 x 64 ----
        wmma::fragment<wmma::accumulator, 16, 16, 16, float> s[2][4];
#pragma unroll
        for (int fr = 0; fr < 2; fr++)
#pragma unroll
            for (int fc = 0; fc < 4; fc++) wmma::fill_fragment(s[fr][fc], 0.f);

#pragma unroll
        for (int kk = 0; kk < 64; kk += 16) {
            wmma::fragment<wmma::matrix_a, 16, 16, 16, __half, wmma::row_major> a_h[2], a_l[2];
#pragma unroll
            for (int fr = 0; fr < 2; fr++) {
                wmma::load_matrix_sync(a_h[fr], Qh + (warp * 32 + fr * 16) * LDH + kk, LDH);
                wmma::load_matrix_sync(a_l[fr], Ql + (warp * 32 + fr * 16) * LDH + kk, LDH);
            }
#pragma unroll
            for (int fc = 0; fc < 4; fc++) {
                wmma::fragment<wmma::matrix_b, 16, 16, 16, __half, wmma::col_major> b_h, b_l;
                wmma::load_matrix_sync(b_h, Kh + (fc * 16) * LDH + kk, LDH);
                wmma::load_matrix_sync(b_l, Kl + (fc * 16) * LDH + kk, LDH);
#pragma unroll
                for (int fr = 0; fr < 2; fr++) {
                    wmma::mma_sync(s[fr][fc], a_h[fr], b_h, s[fr][fc]);
                    wmma::mma_sync(s[fr][fc], a_l[fr], b_h, s[fr][fc]);
                    wmma::mma_sync(s[fr][fc], a_h[fr], b_l, s[fr][fc]);
                }
            }
        }

        // ---- exp in fragments, store P hi/lo (warp-local rows) ----
#pragma unroll
        for (int fr = 0; fr < 2; fr++) {
#pragma unroll
            for (int fc = 0; fc < 4; fc++) {
                if (paired) {
#pragma unroll
                    for (int i = 0; i < 8; i += 2) {
                        const int row = warp * 32 + fr * 16 + er[i];
                        const float m = mreg[fr][i];
                        float p0 = __expf(fmaf(s[fr][fc].x[i],     0.125f, -m));
                        float p1 = __expf(fmaf(s[fr][fc].x[i + 1], 0.125f, -m));
                        lacc[fr][i]     += p0;
                        lacc[fr][i + 1] += p1;
                        const int col = fc * 16 + ec[i];
                        *(uint32_t*)(Ph + row * LDH + col) = packh2(p0, p1);
                        *(uint32_t*)(Pl + row * LDH + col) =
                            packh2(p0 - f16hi(p0), p1 - f16hi(p1));
                    }
                } else {
#pragma unroll
                    for (int i = 0; i < 8; i++) {
                        const int row = warp * 32 + fr * 16 + er[i];
                        const float m = mreg[fr][i];
                        float p = __expf(fmaf(s[fr][fc].x[i], 0.125f, -m));
                        lacc[fr][i] += p;
                        const int col = fc * 16 + ec[i];
                        float ph = f16hi(p);
                        Ph[row * LDH + col] = __float2half_rn(p);
                        Pl[row * LDH + col] = __float2half_rn(p - ph);
                    }
                }
            }
        }

        // store prefetched K tile into alternate buffer
        if (j + 1 < NT) {
            __half* nKh = KhB[1 - cb];
            __half* nKl = KlB[1 - cb];
#pragma unroll
            for (int c = 0; c < 4; c++) {
                *(uint4*)(nKh + kr * LDH + kc * 32 + c * 8) = pf_h[c];
                *(uint4*)(nKl + kr * LDH + kc * 32 + c * 8) = pf_l[c];
            }
        }

        __syncwarp();  // P stores visible to all lanes before fragment loads

        // ---- O += P V (3-term fp16), V = K tile row-major, warp-local P ----
#pragma unroll
        for (int kk = 0; kk < 64; kk += 16) {
            wmma::fragment<wmma::matrix_a, 16, 16, 16, __half, wmma::row_major> p_h[2], p_l[2];
#pragma unroll
            for (int fr = 0; fr < 2; fr++) {
                wmma::load_matrix_sync(p_h[fr], Ph + (warp * 32 + fr * 16) * LDH + kk, LDH);
                wmma::load_matrix_sync(p_l[fr], Pl + (warp * 32 + fr * 16) * LDH + kk, LDH);
            }
#pragma unroll
            for (int fc = 0; fc < 4; fc++) {
                wmma::fragment<wmma::matrix_b, 16, 16, 16, __half, wmma::row_major> v_h, v_l;
                wmma::load_matrix_sync(v_h, Kh + kk * LDH + fc * 16, LDH);
                wmma::load_matrix_sync(v_l, Kl + kk * LDH + fc * 16, LDH);
#pragma unroll
                for (int fr = 0; fr < 2; fr++) {
                    wmma::mma_sync(o[fr][fc], p_h[fr], v_h, o[fr][fc]);
                    wmma::mma_sync(o[fr][fc], p_l[fr], v_h, o[fr][fc]);
                    wmma::mma_sync(o[fr][fc], p_h[fr], v_l, o[fr][fc]);
                }
            }
        }
    }

    // ---- commit row sums ----
#pragma unroll
    for (int fr = 0; fr < 2; fr++)
#pragma unroll
        for (int i = 0; i < 8; i++)
            atomicAdd(&lrow[warp * 32 + fr * 16 + er[i]], lacc[fr][i]);

    // ---- store O fragments (warp-local rows) into fp32 buffer (reuse P) ----
    float* Pf = (float*)(dsm + OPH);  // 128 x LDF
#pragma unroll
    for (int fr = 0; fr < 2; fr++)
#pragma unroll
        for (int fc = 0; fc < 4; fc++)
            wmma::store_matrix_sync(Pf + (warp * 32 + fr * 16) * LDF + fc * 16,
                                    o[fr][fc], LDF, wmma::mem_row_major);
    __syncthreads();

    // ---- epilogue: out = O / l ----
    float* obase = out + (size_t)b * SS * DD + (size_t)h * HD;
#pragma unroll
    for (int i = tid; i < 2048; i += 128) {
        int r = i >> 4, c4 = (i & 15) << 2;
        float inv = 1.f / lrow[r];
        float4 v = *(float4*)(Pf + r * LDF + c4);
        v.x *= inv; v.y *= inv; v.z *= inv; v.w *= inv;
        *(float4*)(obase + (size_t)(qblk * 128 + r) * DD + c4) = v;
    }
}

extern "C" void kernel_launch(void* const* d_in, const int* in_sizes, int n_in,
                              void* d_out, int out_size) {
    const float* x  = (const float*)d_in[0];
    const float* Wq = (const float*)d_in[1];
    float* out = (float*)d_out;

    cudaFuncSetAttribute(attn_kernel, cudaFuncAttributeMaxDynamicSharedMemorySize, ATTN_SMEM_BYTES);

    qproj_kernel<<<dim3(128, 8), 256>>>(x, Wq);
    attn_kernel<<<dim3(SS / 128, BB * HH), 128, ATTN_SMEM_BYTES>>>(out);
}

// round 12
// speedup vs baseline: 1.3070x; 1.3070x over previous
#include <cuda_runtime.h>
#include <cuda_fp16.h>
#include <mma.h>
#include <cstdint>

using namespace nvcuda;

#define BB 4
#define SS 2048
#define DD 512
#define HH 8
#define HD 64
#define LDH 72            // halves per row (144 B) for all SMEM tiles
#define ROWB 144          // row bytes

// q = x @ Wq, pre-split into fp16 hi/lo pairs (packed half2 per uint32)
__device__ uint32_t g_qh[(size_t)BB * SS * DD / 2];
__device__ uint32_t g_ql[(size_t)BB * SS * DD / 2];

__device__ __forceinline__ float f16hi(float v) {
    return __half2float(__float2half_rn(v));
}
__device__ __forceinline__ uint32_t packh2(float a, float b) {
    __half2 h = __floats2half2_rn(a, b);
    return *(uint32_t*)&h;
}
__device__ __forceinline__ uint32_t smem_u32(const void* p) {
    uint32_t a;
    asm("{ .reg .u64 t; cvta.to.shared.u64 t, %1; cvt.u32.u64 %0, t; }" : "=r"(a) : "l"(p));
    return a;
}

#define CP16(dst, src) \
    asm volatile("cp.async.cg.shared.global [%0], [%1], 16;" \
        :: "r"(dst), "l"(src) : "memory")
#define CP_COMMIT() asm volatile("cp.async.commit_group;" ::: "memory")
#define CP_WAIT(N)  asm volatile("cp.async.wait_group %0;" :: "n"(N) : "memory")

#define LDMX4(d, a) \
    asm volatile("ldmatrix.sync.aligned.m8n8.x4.shared.b16 {%0,%1,%2,%3}, [%4];" \
        : "=r"((d)[0]), "=r"((d)[1]), "=r"((d)[2]), "=r"((d)[3]) : "r"(a))
#define LDMX4T(d, a) \
    asm volatile("ldmatrix.sync.aligned.m8n8.x4.trans.shared.b16 {%0,%1,%2,%3}, [%4];" \
        : "=r"((d)[0]), "=r"((d)[1]), "=r"((d)[2]), "=r"((d)[3]) : "r"(a))

#define MMA16816(c, a, b0, b1) \
    asm volatile("mma.sync.aligned.m16n8k16.row.col.f32.f16.f16.f32 " \
        "{%0,%1,%2,%3}, {%4,%5,%6,%7}, {%8,%9}, {%0,%1,%2,%3};" \
        : "+f"((c)[0]), "+f"((c)[1]), "+f"((c)[2]), "+f"((c)[3]) \
        : "r"((a)[0]), "r"((a)[1]), "r"((a)[2]), "r"((a)[3]), "r"(b0), "r"(b1))

// ---------------------------------------------------------------------------
// Kernel 1: q = x @ Wq  via fp16 wmma, 3-term split (hi,lo).  (unchanged)
// ---------------------------------------------------------------------------
#define QLDF 68
__global__ __launch_bounds__(256) void qproj_kernel(const float* __restrict__ x,
                                                    const float* __restrict__ w) {
    __shared__ __align__(16) __half Ah[64 * LDH];
    __shared__ __align__(16) __half Al[64 * LDH];
    __shared__ __align__(16) __half Bh[64 * LDH];
    __shared__ __align__(16) __half Bl[64 * LDH];

    const int tid  = threadIdx.x;
    const int warp = tid >> 5;
    const int tr   = warp >> 1;
    const int tcb  = (warp & 1) * 2;
    const int bm   = blockIdx.x;
    const int bn   = blockIdx.y;

    wmma::fragment<wmma::accumulator, 16, 16, 16, float> c[2];
    wmma::fill_fragment(c[0], 0.f);
    wmma::fill_fragment(c[1], 0.f);

    const float* xbase = x + (size_t)bm * 64 * DD;

    for (int k0 = 0; k0 < DD; k0 += 64) {
#pragma unroll
        for (int i = tid; i < 1024; i += 256) {
            int rr = i >> 4, c4 = (i & 15) << 2;
            float4 a = *(const float4*)(xbase + (size_t)rr * DD + k0 + c4);
            float4 b = *(const float4*)(w + (size_t)(k0 + rr) * DD + bn * 64 + c4);
            uint32_t* Ahp = (uint32_t*)(Ah + rr * LDH + c4);
            uint32_t* Alp = (uint32_t*)(Al + rr * LDH + c4);
            uint32_t* Bhp = (uint32_t*)(Bh + rr * LDH + c4);
            uint32_t* Blp = (uint32_t*)(Bl + rr * LDH + c4);
            Ahp[0] = packh2(a.x, a.y);
            Ahp[1] = packh2(a.z, a.w);
            Alp[0] = packh2(a.x - f16hi(a.x), a.y - f16hi(a.y));
            Alp[1] = packh2(a.z - f16hi(a.z), a.w - f16hi(a.w));
            Bhp[0] = packh2(b.x, b.y);
            Bhp[1] = packh2(b.z, b.w);
            Blp[0] = packh2(b.x - f16hi(b.x), b.y - f16hi(b.y));
            Blp[1] = packh2(b.z - f16hi(b.z), b.w - f16hi(b.w));
        }
        __syncthreads();

#pragma unroll
        for (int kk = 0; kk < 64; kk += 16) {
            wmma::fragment<wmma::matrix_a, 16, 16, 16, __half, wmma::row_major> a_h, a_l;
            wmma::load_matrix_sync(a_h, Ah + tr * 16 * LDH + kk, LDH);
            wmma::load_matrix_sync(a_l, Al + tr * 16 * LDH + kk, LDH);
#pragma unroll
            for (int t = 0; t < 2; t++) {
                wmma::fragment<wmma::matrix_b, 16, 16, 16, __half, wmma::row_major> b_h, b_l;
                wmma::load_matrix_sync(b_h, Bh + kk * LDH + (tcb + t) * 16, LDH);
                wmma::load_matrix_sync(b_l, Bl + kk * LDH + (tcb + t) * 16, LDH);
                wmma::mma_sync(c[t], a_h, b_h, c[t]);
                wmma::mma_sync(c[t], a_l, b_h, c[t]);
                wmma::mma_sync(c[t], a_h, b_l, c[t]);
            }
        }
        __syncthreads();
    }

    float* Cs = (float*)Ah;
#pragma unroll
    for (int t = 0; t < 2; t++)
        wmma::store_matrix_sync(Cs + tr * 16 * QLDF + (tcb + t) * 16, c[t], QLDF, wmma::mem_row_major);
    __syncthreads();

#pragma unroll
    for (int i = tid; i < 2048; i += 256) {
        int rr = i >> 5, wv = i & 31;
        float c0 = Cs[rr * QLDF + 2 * wv];
        float c1 = Cs[rr * QLDF + 2 * wv + 1];
        size_t word = (size_t)(bm * 64 + rr) * (DD / 2) + bn * 32 + wv;
        g_qh[word] = packh2(c0, c1);
        g_ql[word] = packh2(c0 - f16hi(c0), c1 - f16hi(c1));
    }
}

// ---------------------------------------------------------------------------
// Kernel 2: flash attention via raw mma.m16n8k16 + ldmatrix.
// CTA: 128 threads / 4 warps, each warp strip 32(q) x 64(k).
// P stays in registers (C->A fragment identity). Row sums in registers.
// K/V tiles cp.async double-buffered. Static per-row shift m_i = |q_i|^2/8.
// ---------------------------------------------------------------------------
#define OQH  0u
#define OQL  18432u
#define OK0H 36864u
#define OK0L 46080u
#define OK1H 55296u
#define OK1L 64512u
#define OMR  73728u
#define ATTN_SMEM_BYTES 74240

__global__ __launch_bounds__(128, 2) void attn_kernel(float* __restrict__ out) {
    extern __shared__ __align__(16) char dsm[];
    const uint32_t sQh = smem_u32(dsm) + OQH;
    const uint32_t sQl = smem_u32(dsm) + OQL;
    const uint32_t sKh[2] = { smem_u32(dsm) + OK0H, smem_u32(dsm) + OK1H };
    const uint32_t sKl[2] = { smem_u32(dsm) + OK0L, smem_u32(dsm) + OK1L };
    float* smrow = (float*)(dsm + OMR);

    const int tid  = threadIdx.x;
    const int warp = tid >> 5;
    const int lane = tid & 31;
    const int g    = lane >> 2;        // group row 0..7
    const int sub  = lane >> 3;        // ldmatrix sub-matrix 0..3
    const int l7   = lane & 7;
    const int qblk = blockIdx.x;       // 0..15
    const int bh   = blockIdx.y;       // 0..31
    const int b = bh >> 3, h = bh & 7;

    // ---- issue Q tile (128 x 64) via cp.async: thread = one row ----
    {
        const uint32_t* srcH = g_qh + (size_t)(b * SS + qblk * 128 + tid) * (DD / 2) + h * 32;
        const uint32_t* srcL = g_ql + (size_t)(b * SS + qblk * 128 + tid) * (DD / 2) + h * 32;
        uint32_t dH = sQh + tid * ROWB;
        uint32_t dL = sQl + tid * ROWB;
#pragma unroll
        for (int c = 0; c < 8; c++) {
            CP16(dH + c * 16, srcH + c * 4);
            CP16(dL + c * 16, srcL + c * 4);
        }
        CP_COMMIT();
    }
    // ---- issue K tiles 0,1 into buffers 0,1 ----
    const int kvr = tid >> 1, kvc = tid & 1;   // row, half-of-row
#pragma unroll
    for (int t0 = 0; t0 < 2; t0++) {
        const uint32_t* srcH = g_qh + (size_t)(b * SS + t0 * 64 + kvr) * (DD / 2) + h * 32 + kvc * 16;
        const uint32_t* srcL = g_ql + (size_t)(b * SS + t0 * 64 + kvr) * (DD / 2) + h * 32 + kvc * 16;
        uint32_t dH = sKh[t0] + kvr * ROWB + kvc * 64;
        uint32_t dL = sKl[t0] + kvr * ROWB + kvc * 64;
#pragma unroll
        for (int c = 0; c < 4; c++) {
            CP16(dH + c * 16, srcH + c * 4);
            CP16(dL + c * 16, srcL + c * 4);
        }
        CP_COMMIT();
    }

    CP_WAIT(2);            // Q arrived (K0,K1 may be in flight)
    __syncthreads();

    // ---- per-row static shift m_i = 0.125 * |q_i|^2 ----
    {
        const __half* qhr = (const __half*)(dsm + OQH) + tid * LDH;
        const __half* qlr = (const __half*)(dsm + OQL) + tid * LDH;
        float n2 = 0.f;
#pragma unroll
        for (int c = 0; c < 64; c++) {
            float v = __half2float(qhr[c]) + __half2float(qlr[c]);
            n2 = fmaf(v, v, n2);
        }
        smrow[tid] = 0.125f * n2;
    }
    __syncthreads();

    // per-lane shifts for its 4 rows (2 frs x rows g, g+8)
    float mr[2][2];
#pragma unroll
    for (int fr = 0; fr < 2; fr++) {
        mr[fr][0] = smrow[warp * 32 + fr * 16 + g];
        mr[fr][1] = smrow[warp * 32 + fr * 16 + 8 + g];
    }

    // ldmatrix lane-address components
    const uint32_t aRow = (uint32_t)((sub & 1) * 8 + l7);        // A: m0 r0-7,c0 | m1 r8-15,c0 | m2 r0-7,c8 | m3 r8-15,c8
    const uint32_t aCol = (uint32_t)((sub >> 1) * 16);           // bytes
    const uint32_t bRow = (uint32_t)((sub >> 1) * 8 + l7);       // B(S): m0 n0-7,c0 | m1 n0-7,c8 | m2 n8-15,c0 | m3 n8-15,c8
    const uint32_t bCol = (uint32_t)((sub & 1) * 16);
    const uint32_t vRow = (uint32_t)((sub & 1) * 8 + l7);        // B(V,trans): m0 k0-7,n0 | m1 k8-15,n0 | m2 k0-7,n8 | m3 k8-15,n8
    const uint32_t vCol = (uint32_t)((sub >> 1) * 16);

    const uint32_t qA = sQh + (warp * 32 + aRow) * ROWB + aCol;  // + fr*16*ROWB + kk*32
    const uint32_t qAl = sQl + (warp * 32 + aRow) * ROWB + aCol;

    float o[2][8][4];
#pragma unroll
    for (int fr = 0; fr < 2; fr++)
#pragma unroll
        for (int c = 0; c < 8; c++)
#pragma unroll
            for (int i = 0; i < 4; i++) o[fr][c][i] = 0.f;

    float lacc[2][2] = { {0.f, 0.f}, {0.f, 0.f} };

    const int NT = SS / 64;
    for (int j = 0; j < NT; j++) {
        const int cb = j & 1;
        if (j + 2 < NT) CP_WAIT(1); else CP_WAIT(0);
        __syncthreads();

        const uint32_t bH = sKh[cb] + bRow * ROWB + bCol;   // + nb*16*ROWB + kk*32
        const uint32_t bL = sKl[cb] + bRow * ROWB + bCol;

        // ---- S = Q K^T (3-term fp16) ----
        float sc[2][8][4];
#pragma unroll
        for (int fr = 0; fr < 2; fr++)
#pragma unroll
            for (int c = 0; c < 8; c++)
#pragma unroll
                for (int i = 0; i < 4; i++) sc[fr][c][i] = 0.f;

#pragma unroll
        for (int kk = 0; kk < 4; kk++) {
            uint32_t ah[2][4], al[2][4];
#pragma unroll
            for (int fr = 0; fr < 2; fr++) {
                LDMX4(ah[fr], qA  + fr * 16 * ROWB + kk * 32);
                LDMX4(al[fr], qAl + fr * 16 * ROWB + kk * 32);
            }
#pragma unroll
            for (int nb = 0; nb < 4; nb++) {
                uint32_t kh[4], kl[4];
                LDMX4(kh, bH + nb * 16 * ROWB + kk * 32);
                LDMX4(kl, bL + nb * 16 * ROWB + kk * 32);
#pragma unroll
                for (int fr = 0; fr < 2; fr++) {
                    MMA16816(sc[fr][2 * nb],     ah[fr], kh[0], kh[1]);
                    MMA16816(sc[fr][2 * nb],     al[fr], kh[0], kh[1]);
                    MMA16816(sc[fr][2 * nb],     ah[fr], kl[0], kl[1]);
                    MMA16816(sc[fr][2 * nb + 1], ah[fr], kh[2], kh[3]);
                    MMA16816(sc[fr][2 * nb + 1], al[fr], kh[2], kh[3]);
                    MMA16816(sc[fr][2 * nb + 1], ah[fr], kl[2], kl[3]);
                }
            }
        }

        // ---- exp in registers; pack P directly into A-operand fragments ----
        uint32_t pah[2][4][4], pal[2][4][4];
#pragma unroll
        for (int fr = 0; fr < 2; fr++) {
#pragma unroll
            for (int c = 0; c < 8; c++) {
                float p0 = __expf(fmaf(sc[fr][c][0], 0.125f, -mr[fr][0]));
                float p1 = __expf(fmaf(sc[fr][c][1], 0.125f, -mr[fr][0]));
                float p2 = __expf(fmaf(sc[fr][c][2], 0.125f, -mr[fr][1]));
                float p3 = __expf(fmaf(sc[fr][c][3], 0.125f, -mr[fr][1]));
                lacc[fr][0] += p0 + p1;
                lacc[fr][1] += p2 + p3;
                const int ks = c >> 1, r2 = (c & 1) * 2;
                pah[fr][ks][r2]     = packh2(p0, p1);
                pah[fr][ks][r2 + 1] = packh2(p2, p3);
                pal[fr][ks][r2]     = packh2(p0 - f16hi(p0), p1 - f16hi(p1));
                pal[fr][ks][r2 + 1] = packh2(p2 - f16hi(p2), p3 - f16hi(p3));
            }
        }

        // ---- O += P V (3-term), V = K tile via ldmatrix.trans ----
        const uint32_t vH = sKh[cb] + vRow * ROWB + vCol;   // + ks*16*ROWB + nb*32
        const uint32_t vL = sKl[cb] + vRow * ROWB + vCol;
#pragma unroll
        for (int ks = 0; ks < 4; ks++) {
#pragma unroll
            for (int nb = 0; nb < 4; nb++) {
                uint32_t vh[4], vl[4];
                LDMX4T(vh, vH + ks * 16 * ROWB + nb * 32);
                LDMX4T(vl, vL + ks * 16 * ROWB + nb * 32);
#pragma unroll
                for (int fr = 0; fr < 2; fr++) {
                    MMA16816(o[fr][2 * nb],     pah[fr][ks], vh[0], vh[1]);
                    MMA16816(o[fr][2 * nb],     pal[fr][ks], vh[0], vh[1]);
                    MMA16816(o[fr][2 * nb],     pah[fr][ks], vl[0], vl[1]);
                    MMA16816(o[fr][2 * nb + 1], pah[fr][ks], vh[2], vh[3]);
                    MMA16816(o[fr][2 * nb + 1], pal[fr][ks], vh[2], vh[3]);
                    MMA16816(o[fr][2 * nb + 1], pah[fr][ks], vl[2], vl[3]);
                }
            }
        }

        __syncthreads();   // all warps done reading buffer cb

        // ---- issue K tile j+2 into buffer cb ----
        if (j + 2 < NT) {
            const uint32_t* srcH = g_qh + (size_t)(b * SS + (j + 2) * 64 + kvr) * (DD / 2) + h * 32 + kvc * 16;
            const uint32_t* srcL = g_ql + (size_t)(b * SS + (j + 2) * 64 + kvr) * (DD / 2) + h * 32 + kvc * 16;
            uint32_t dH = sKh[cb] + kvr * ROWB + kvc * 64;
            uint32_t dL = sKl[cb] + kvr * ROWB + kvc * 64;
#pragma unroll
            for (int c = 0; c < 4; c++) {
                CP16(dH + c * 16, srcH + c * 4);
                CP16(dL + c * 16, srcL + c * 4);
            }
            CP_COMMIT();
        }
    }

    // ---- row sums: reduce over quad (lanes t=0..3 share rows) ----
    float inv[2][2];
#pragma unroll
    for (int fr = 0; fr < 2; fr++)
#pragma unroll
        for (int rr = 0; rr < 2; rr++) {
            float s = lacc[fr][rr];
            s += __shfl_xor_sync(0xFFFFFFFFu, s, 1);
            s += __shfl_xor_sync(0xFFFFFFFFu, s, 2);
            inv[fr][rr] = 1.f / s;
        }

    // ---- epilogue: out = O / l, direct from registers ----
    const int t = lane & 3;
#pragma unroll
    for (int fr = 0; fr < 2; fr++) {
        const int row0 = qblk * 128 + warp * 32 + fr * 16 + g;
        float* op0 = out + ((size_t)b * SS + row0) * DD + h * HD;
        float* op1 = op0 + 8 * DD;
#pragma unroll
        for (int c = 0; c < 8; c++) {
            float2 v0 = make_float2(o[fr][c][0] * inv[fr][0], o[fr][c][1] * inv[fr][0]);
            float2 v1 = make_float2(o[fr][c][2] * inv[fr][1], o[fr][c][3] * inv[fr][1]);
            *(float2*)(op0 + c * 8 + 2 * t) = v0;
            *(float2*)(op1 + c * 8 + 2 * t) = v1;
        }
    }
}

extern "C" void kernel_launch(void* const* d_in, const int* in_sizes, int n_in,
                              void* d_out, int out_size) {
    const float* x  = (const float*)d_in[0];
    const float* Wq = (const float*)d_in[1];
    float* out = (float*)d_out;

    cudaFuncSetAttribute(attn_kernel, cudaFuncAttributeMaxDynamicSharedMemorySize, ATTN_SMEM_BYTES);

    qproj_kernel<<<dim3(128, 8), 256>>>(x, Wq);
    attn_kernel<<<dim3(SS / 128, BB * HH), 128, ATTN_SMEM_BYTES>>>(out);
}